// round 3
// baseline (speedup 1.0000x reference)
#include <cuda_runtime.h>

#define NMAX 50000
#define D 128
#define D4 32          // 128 floats = 32 float4
#define BN_EPS 1e-5f

// ---------------- scratch (device globals; no allocation allowed) ----------------
__device__ float4 g_h[NMAX * D4];      // h = x * rsqrt(deg_out)   (25.6 MB)
__device__ float4 g_agg[NMAX * D4];    // scatter-add target       (25.6 MB)
__device__ int    g_deg_out[NMAX];
__device__ int    g_deg_in[NMAX];
__device__ float  g_inv_in[NMAX];      // rsqrt(max(deg_in,1))
__device__ float  g_sum[D];            // BN column sums
__device__ float  g_sq[D];             // BN column sum-of-squares
__device__ float  g_scale[D];          // gamma * istd
__device__ float  g_shift[D];          // beta - mean * gamma * istd

// ---------------- 1) zero scratch ----------------
__global__ void zero_kernel(int n4, int N) {
    int i = blockIdx.x * blockDim.x + threadIdx.x;
    if (i < n4) g_agg[i] = make_float4(0.f, 0.f, 0.f, 0.f);
    if (i < N) { g_deg_out[i] = 0; g_deg_in[i] = 0; }
    if (i < D) { g_sum[i] = 0.f; g_sq[i] = 0.f; }
}

// ---------------- 2) degree counts ----------------
__global__ void degree_kernel(const int* __restrict__ src,
                              const int* __restrict__ dst, int nE) {
    int e = blockIdx.x * blockDim.x + threadIdx.x;
    if (e < nE) {
        atomicAdd(&g_deg_out[src[e]], 1);
        atomicAdd(&g_deg_in[dst[e]], 1);
    }
}

// ---------------- 3) h = x * rsqrt(deg_out); also inv_in ----------------
__global__ void hscale_kernel(const float4* __restrict__ x, int N) {
    int t = blockIdx.x * blockDim.x + threadIdx.x;
    int total = N * D4;
    if (t < total) {
        int row = t >> 5;
        float inv = rsqrtf(fmaxf((float)g_deg_out[row], 1.f));
        float4 v = x[t];
        v.x *= inv; v.y *= inv; v.z *= inv; v.w *= inv;
        g_h[t] = v;
    }
    if (t < N) g_inv_in[t] = rsqrtf(fmaxf((float)g_deg_in[t], 1.f));
}

// ---------------- 4) edge scatter: agg[dst] += h[src] (one warp per edge) ------
__global__ void scatter_kernel(const int* __restrict__ src,
                               const int* __restrict__ dst, int nE) {
    int t = blockIdx.x * blockDim.x + threadIdx.x;
    int e = t >> 5;
    if (e >= nE) return;
    int lane = t & 31;
    int s = src[e];
    int d = dst[e];
    float4 v = g_h[s * D4 + lane];
    atomicAdd(&g_agg[d * D4 + lane], v);   // 128-bit vector RED (sm_90+)
}

// ---------------- 5) fused dual GEMM + ReLU + residual + BN partials -----------
// Tile: 64 rows x 128 cols per block, 256 threads, thread tile = 8 rows x 4 cols.
// W and Wr resident in shared (128 KB), row tiles (64 KB) => 192 KB dynamic smem.
// NOTE: g_agg / g_inv_in are referenced via the __device__ symbols INSIDE the
// kernel (taking their address from host code yields the host shadow -> R2 bug).
__global__ void __launch_bounds__(256, 1)
gemm_kernel(const float* __restrict__ x,
            const float* __restrict__ W,  const float* __restrict__ b,
            const float* __restrict__ Wr, const float* __restrict__ br,
            float* __restrict__ y, int N) {
    extern __shared__ float smem[];
    float* sW  = smem;            // 128*128
    float* sWr = smem + 16384;    // 128*128
    float* sA  = smem + 32768;    // 64*128
    float* sX  = smem + 40960;    // 64*128

    int tid = threadIdx.x;
    // Load W, Wr (row-major [k][n]) into shared, float4.
    const float4* W4  = (const float4*)W;
    const float4* Wr4 = (const float4*)Wr;
    float4* sW4  = (float4*)sW;
    float4* sWr4 = (float4*)sWr;
    #pragma unroll
    for (int i = tid; i < 4096; i += 256) { sW4[i] = W4[i]; sWr4[i] = Wr4[i]; }

    int cq = tid & 31;        // col quartet index
    int c  = cq * 4;          // first of 4 columns
    int r0 = (tid >> 5) * 8;  // first of 8 rows

    float4 bb  = *(const float4*)(b  + c);
    float4 bbr = *(const float4*)(br + c);

    int rowbase = blockIdx.x * 64;

    // Load row tiles (agg scaled by inv_in, and x)
    float4* sA4 = (float4*)sA;
    float4* sX4 = (float4*)sX;
    const float4* x4 = (const float4*)x;
    #pragma unroll
    for (int i = tid; i < 2048; i += 256) {
        int lr = i >> 5;
        int gr = rowbase + lr;
        if (gr < N) {
            float inv = g_inv_in[gr];
            float4 a = g_agg[gr * D4 + (i & 31)];
            a.x *= inv; a.y *= inv; a.z *= inv; a.w *= inv;
            sA4[i] = a;
            sX4[i] = x4[gr * D4 + (i & 31)];
        } else {
            float4 z = make_float4(0.f, 0.f, 0.f, 0.f);
            sA4[i] = z;
            sX4[i] = z;
        }
    }
    __syncthreads();

    float accG[8][4], accR[8][4];
    #pragma unroll
    for (int i = 0; i < 8; i++)
        #pragma unroll
        for (int j = 0; j < 4; j++) { accG[i][j] = 0.f; accR[i][j] = 0.f; }

    #pragma unroll 4
    for (int k = 0; k < 128; k++) {
        float4 w  = ((const float4*)(sW  + k * 128))[cq];
        float4 wr = ((const float4*)(sWr + k * 128))[cq];
        #pragma unroll
        for (int i = 0; i < 8; i++) {
            float a  = sA[(r0 + i) * 128 + k];
            float xv = sX[(r0 + i) * 128 + k];
            accG[i][0] = fmaf(a, w.x, accG[i][0]);
            accG[i][1] = fmaf(a, w.y, accG[i][1]);
            accG[i][2] = fmaf(a, w.z, accG[i][2]);
            accG[i][3] = fmaf(a, w.w, accG[i][3]);
            accR[i][0] = fmaf(xv, wr.x, accR[i][0]);
            accR[i][1] = fmaf(xv, wr.y, accR[i][1]);
            accR[i][2] = fmaf(xv, wr.z, accR[i][2]);
            accR[i][3] = fmaf(xv, wr.w, accR[i][3]);
        }
    }

    // Epilogue: y = relu(gcn + b) + relu(res + br); accumulate BN partials.
    float cs0 = 0.f, cs1 = 0.f, cs2 = 0.f, cs3 = 0.f;
    float cq0 = 0.f, cq1 = 0.f, cq2 = 0.f, cq3 = 0.f;
    #pragma unroll
    for (int i = 0; i < 8; i++) {
        int gr = rowbase + r0 + i;
        if (gr < N) {
            float4 o;
            o.x = fmaxf(accG[i][0] + bb.x, 0.f) + fmaxf(accR[i][0] + bbr.x, 0.f);
            o.y = fmaxf(accG[i][1] + bb.y, 0.f) + fmaxf(accR[i][1] + bbr.y, 0.f);
            o.z = fmaxf(accG[i][2] + bb.z, 0.f) + fmaxf(accR[i][2] + bbr.z, 0.f);
            o.w = fmaxf(accG[i][3] + bb.w, 0.f) + fmaxf(accR[i][3] + bbr.w, 0.f);
            *(float4*)(y + gr * D + c) = o;
            cs0 += o.x; cq0 += o.x * o.x;
            cs1 += o.y; cq1 += o.y * o.y;
            cs2 += o.z; cq2 += o.z * o.z;
            cs3 += o.w; cq3 += o.w * o.w;
        }
    }
    atomicAdd(&g_sum[c + 0], cs0); atomicAdd(&g_sq[c + 0], cq0);
    atomicAdd(&g_sum[c + 1], cs1); atomicAdd(&g_sq[c + 1], cq1);
    atomicAdd(&g_sum[c + 2], cs2); atomicAdd(&g_sq[c + 2], cq2);
    atomicAdd(&g_sum[c + 3], cs3); atomicAdd(&g_sq[c + 3], cq3);
}

// ---------------- 6) BN stats -> per-column scale/shift ----------------
__global__ void bnstats_kernel(const float* __restrict__ gamma,
                               const float* __restrict__ beta, float Ninv) {
    int i = threadIdx.x;
    float mean = g_sum[i] * Ninv;
    float var  = fmaxf(g_sq[i] * Ninv - mean * mean, 0.f);
    float istd = rsqrtf(var + BN_EPS);
    float sc = gamma[i] * istd;
    g_scale[i] = sc;
    g_shift[i] = beta[i] - mean * sc;
}

// ---------------- 7) normalize output in place ----------------
__global__ void normalize_kernel(float4* __restrict__ y, int total4) {
    int t = blockIdx.x * blockDim.x + threadIdx.x;
    if (t >= total4) return;
    int cb = (t & 31) * 4;
    float4 v = y[t];
    v.x = fmaf(v.x, g_scale[cb + 0], g_shift[cb + 0]);
    v.y = fmaf(v.y, g_scale[cb + 1], g_shift[cb + 1]);
    v.z = fmaf(v.z, g_scale[cb + 2], g_shift[cb + 2]);
    v.w = fmaf(v.w, g_scale[cb + 3], g_shift[cb + 3]);
    y[t] = v;
}

// ---------------- launch ----------------
extern "C" void kernel_launch(void* const* d_in, const int* in_sizes, int n_in,
                              void* d_out, int out_size) {
    const float* x     = (const float*)d_in[0];
    const int*   src   = (const int*)d_in[1];
    const int*   dst   = (const int*)d_in[2];
    const float* W     = (const float*)d_in[3];
    const float* b     = (const float*)d_in[4];
    const float* Wr    = (const float*)d_in[5];
    const float* br    = (const float*)d_in[6];
    const float* gamma = (const float*)d_in[7];
    const float* beta  = (const float*)d_in[8];
    float* out = (float*)d_out;

    int N  = in_sizes[0] / D;
    int nE = in_sizes[1];
    int n4 = N * D4;

    const int SMEM = 196608;  // 48K floats
    cudaFuncSetAttribute(gemm_kernel, cudaFuncAttributeMaxDynamicSharedMemorySize, SMEM);

    zero_kernel<<<(n4 + 255) / 256, 256>>>(n4, N);
    degree_kernel<<<(nE + 255) / 256, 256>>>(src, dst, nE);
    hscale_kernel<<<(n4 + 255) / 256, 256>>>((const float4*)x, N);
    {
        long long threads = (long long)nE * 32;
        int blocks = (int)((threads + 255) / 256);
        scatter_kernel<<<blocks, 256>>>(src, dst, nE);
    }
    int ntiles = (N + 63) / 64;
    gemm_kernel<<<ntiles, 256, SMEM>>>(x, W, b, Wr, br, out, N);
    bnstats_kernel<<<1, D>>>(gamma, beta, 1.0f / (float)N);
    normalize_kernel<<<(n4 + 255) / 256, 256>>>((float4*)out, n4);
}

// round 4
// speedup vs baseline: 1.5647x; 1.5647x over previous
#include <cuda_runtime.h>

#define NMAX 50000
#define EMAX 800000
#define D 128
#define D4 32          // 128 floats = 32 float4
#define BN_EPS 1e-5f
#define SCAN_BLK 1024
#define SCAN_NB  49    // 49*1024 >= 50000

// ---------------- scratch (device globals; no allocation allowed) ----------------
__device__ float4 g_agg[NMAX * D4];    // gather output (25.6 MB)
__device__ int    g_deg_out[NMAX];
__device__ int    g_deg_in[NMAX];
__device__ int    g_incl[SCAN_NB * SCAN_BLK];   // inclusive scan of deg_in
__device__ int    g_bsum[SCAN_NB];
__device__ int    g_boff[SCAN_NB];
__device__ int    g_rowstart[NMAX];
__device__ int    g_cursor[NMAX];
__device__ int    g_csrc[EMAX];        // src ids sorted by dst (CSR)
__device__ float  g_inv_in[NMAX];
__device__ float  g_inv_out[NMAX];
__device__ float  g_sum[D];
__device__ float  g_sq[D];
__device__ float  g_scale[D];
__device__ float  g_shift[D];

// ---------------- 1) zero degrees + BN sums ----------------
__global__ void zero_kernel(int N) {
    int i = blockIdx.x * blockDim.x + threadIdx.x;
    if (i < N) { g_deg_out[i] = 0; g_deg_in[i] = 0; }
    if (i < D) { g_sum[i] = 0.f; g_sq[i] = 0.f; }
}

// ---------------- 2) degree counts ----------------
__global__ void degree_kernel(const int* __restrict__ src,
                              const int* __restrict__ dst, int nE) {
    int e = blockIdx.x * blockDim.x + threadIdx.x;
    if (e < nE) {
        atomicAdd(&g_deg_out[src[e]], 1);
        atomicAdd(&g_deg_in[dst[e]], 1);
    }
}

// ---------------- 3a) per-block inclusive scan of deg_in ----------------
__global__ void scan1_kernel(int N) {
    __shared__ int sh[SCAN_BLK];
    int t = threadIdx.x;
    int i = blockIdx.x * SCAN_BLK + t;
    int v = (i < N) ? g_deg_in[i] : 0;
    sh[t] = v;
    __syncthreads();
    #pragma unroll
    for (int off = 1; off < SCAN_BLK; off <<= 1) {
        int tv = (t >= off) ? sh[t - off] : 0;
        __syncthreads();
        sh[t] += tv;
        __syncthreads();
    }
    g_incl[i] = sh[t];
    if (t == SCAN_BLK - 1) g_bsum[blockIdx.x] = sh[t];
}

// ---------------- 3b) exclusive scan of block sums (tiny) ----------------
__global__ void scan2_kernel() {
    if (threadIdx.x == 0) {
        int run = 0;
        for (int i = 0; i < SCAN_NB; i++) { g_boff[i] = run; run += g_bsum[i]; }
    }
}

// ---------------- 3c) finalize row_start / cursor / inv degs ----------------
__global__ void scan3_kernel(int N) {
    int i = blockIdx.x * SCAN_BLK + threadIdx.x;
    if (i >= N) return;
    int din = g_deg_in[i];
    int rs = g_incl[i] - din + g_boff[blockIdx.x];
    g_rowstart[i] = rs;
    g_cursor[i]   = rs;
    g_inv_in[i]  = rsqrtf(fmaxf((float)din, 1.f));
    g_inv_out[i] = rsqrtf(fmaxf((float)g_deg_out[i], 1.f));
}

// ---------------- 4) CSR fill: bucket src ids by dst ----------------
__global__ void fill_kernel(const int* __restrict__ src,
                            const int* __restrict__ dst, int nE) {
    int e = blockIdx.x * blockDim.x + threadIdx.x;
    if (e < nE) {
        int pos = atomicAdd(&g_cursor[dst[e]], 1);
        g_csrc[pos] = src[e];
    }
}

// ---------------- 5) gather: agg[d] = inv_in[d] * sum_{e in CSR[d]} x[src]*inv_out[src]
// One warp per destination node. Lane l owns feature chunk l (float4).
__global__ void gather_kernel(const float4* __restrict__ x4, int N) {
    int w = (blockIdx.x * blockDim.x + threadIdx.x) >> 5;
    int lane = threadIdx.x & 31;
    if (w >= N) return;
    int start = g_rowstart[w];
    int deg   = g_deg_in[w];
    float4 acc = make_float4(0.f, 0.f, 0.f, 0.f);
    for (int base = 0; base < deg; base += 32) {
        int rem = deg - base;
        int cnt = rem < 32 ? rem : 32;
        int sIdx = 0;
        if (lane < cnt) sIdx = g_csrc[start + base + lane];
        #pragma unroll 4
        for (int j = 0; j < cnt; j++) {
            int s = __shfl_sync(0xffffffffu, sIdx, j);
            float sc = __ldg(&g_inv_out[s]);          // broadcast (same addr all lanes)
            float4 v = x4[s * D4 + lane];
            acc.x = fmaf(v.x, sc, acc.x);
            acc.y = fmaf(v.y, sc, acc.y);
            acc.z = fmaf(v.z, sc, acc.z);
            acc.w = fmaf(v.w, sc, acc.w);
        }
    }
    float inv = g_inv_in[w];
    acc.x *= inv; acc.y *= inv; acc.z *= inv; acc.w *= inv;
    g_agg[w * D4 + lane] = acc;
}

// ---------------- 6) fused dual GEMM + ReLU + residual + BN partials -----------
// Tile: 64 rows x 128 cols per block, 256 threads, thread tile = 8 rows x 4 cols.
__global__ void __launch_bounds__(256, 1)
gemm_kernel(const float* __restrict__ x,
            const float* __restrict__ W,  const float* __restrict__ b,
            const float* __restrict__ Wr, const float* __restrict__ br,
            float* __restrict__ y, int N) {
    extern __shared__ float smem[];
    float* sW  = smem;            // 128*128
    float* sWr = smem + 16384;    // 128*128
    float* sA  = smem + 32768;    // 64*128
    float* sX  = smem + 40960;    // 64*128
    __shared__ float bnS[D];
    __shared__ float bnQ[D];

    int tid = threadIdx.x;
    if (tid < D) { bnS[tid] = 0.f; bnQ[tid] = 0.f; }

    const float4* W4  = (const float4*)W;
    const float4* Wr4 = (const float4*)Wr;
    float4* sW4  = (float4*)sW;
    float4* sWr4 = (float4*)sWr;
    #pragma unroll
    for (int i = tid; i < 4096; i += 256) { sW4[i] = W4[i]; sWr4[i] = Wr4[i]; }

    int cq = tid & 31;        // col quartet index
    int c  = cq * 4;
    int r0 = (tid >> 5) * 8;

    float4 bb  = *(const float4*)(b  + c);
    float4 bbr = *(const float4*)(br + c);

    int rowbase = blockIdx.x * 64;

    float4* sA4 = (float4*)sA;
    float4* sX4 = (float4*)sX;
    const float4* x4 = (const float4*)x;
    #pragma unroll
    for (int i = tid; i < 2048; i += 256) {
        int lr = i >> 5;
        int gr = rowbase + lr;
        if (gr < N) {
            sA4[i] = g_agg[gr * D4 + (i & 31)];   // inv_in already applied in gather
            sX4[i] = x4[gr * D4 + (i & 31)];
        } else {
            float4 z = make_float4(0.f, 0.f, 0.f, 0.f);
            sA4[i] = z;
            sX4[i] = z;
        }
    }
    __syncthreads();

    float accG[8][4], accR[8][4];
    #pragma unroll
    for (int i = 0; i < 8; i++)
        #pragma unroll
        for (int j = 0; j < 4; j++) { accG[i][j] = 0.f; accR[i][j] = 0.f; }

    #pragma unroll 4
    for (int k = 0; k < 128; k++) {
        float4 w  = ((const float4*)(sW  + k * 128))[cq];
        float4 wr = ((const float4*)(sWr + k * 128))[cq];
        #pragma unroll
        for (int i = 0; i < 8; i++) {
            float a  = sA[(r0 + i) * 128 + k];
            float xv = sX[(r0 + i) * 128 + k];
            accG[i][0] = fmaf(a, w.x, accG[i][0]);
            accG[i][1] = fmaf(a, w.y, accG[i][1]);
            accG[i][2] = fmaf(a, w.z, accG[i][2]);
            accG[i][3] = fmaf(a, w.w, accG[i][3]);
            accR[i][0] = fmaf(xv, wr.x, accR[i][0]);
            accR[i][1] = fmaf(xv, wr.y, accR[i][1]);
            accR[i][2] = fmaf(xv, wr.z, accR[i][2]);
            accR[i][3] = fmaf(xv, wr.w, accR[i][3]);
        }
    }

    float cs0 = 0.f, cs1 = 0.f, cs2 = 0.f, cs3 = 0.f;
    float cq0 = 0.f, cq1 = 0.f, cq2 = 0.f, cq3 = 0.f;
    #pragma unroll
    for (int i = 0; i < 8; i++) {
        int gr = rowbase + r0 + i;
        if (gr < N) {
            float4 o;
            o.x = fmaxf(accG[i][0] + bb.x, 0.f) + fmaxf(accR[i][0] + bbr.x, 0.f);
            o.y = fmaxf(accG[i][1] + bb.y, 0.f) + fmaxf(accR[i][1] + bbr.y, 0.f);
            o.z = fmaxf(accG[i][2] + bb.z, 0.f) + fmaxf(accR[i][2] + bbr.z, 0.f);
            o.w = fmaxf(accG[i][3] + bb.w, 0.f) + fmaxf(accR[i][3] + bbr.w, 0.f);
            *(float4*)(y + gr * D + c) = o;
            cs0 += o.x; cq0 += o.x * o.x;
            cs1 += o.y; cq1 += o.y * o.y;
            cs2 += o.z; cq2 += o.z * o.z;
            cs3 += o.w; cq3 += o.w * o.w;
        }
    }
    // block-local BN reduction (shared atomics), then 128 global atomics per block
    atomicAdd(&bnS[c + 0], cs0); atomicAdd(&bnQ[c + 0], cq0);
    atomicAdd(&bnS[c + 1], cs1); atomicAdd(&bnQ[c + 1], cq1);
    atomicAdd(&bnS[c + 2], cs2); atomicAdd(&bnQ[c + 2], cq2);
    atomicAdd(&bnS[c + 3], cs3); atomicAdd(&bnQ[c + 3], cq3);
    __syncthreads();
    if (tid < D) {
        atomicAdd(&g_sum[tid], bnS[tid]);
        atomicAdd(&g_sq[tid],  bnQ[tid]);
    }
}

// ---------------- 7) BN stats -> per-column scale/shift ----------------
__global__ void bnstats_kernel(const float* __restrict__ gamma,
                               const float* __restrict__ beta, float Ninv) {
    int i = threadIdx.x;
    float mean = g_sum[i] * Ninv;
    float var  = fmaxf(g_sq[i] * Ninv - mean * mean, 0.f);
    float istd = rsqrtf(var + BN_EPS);
    float sc = gamma[i] * istd;
    g_scale[i] = sc;
    g_shift[i] = beta[i] - mean * sc;
}

// ---------------- 8) normalize output in place ----------------
__global__ void normalize_kernel(float4* __restrict__ y, int total4) {
    int t = blockIdx.x * blockDim.x + threadIdx.x;
    if (t >= total4) return;
    int cb = (t & 31) * 4;
    float4 v = y[t];
    v.x = fmaf(v.x, g_scale[cb + 0], g_shift[cb + 0]);
    v.y = fmaf(v.y, g_scale[cb + 1], g_shift[cb + 1]);
    v.z = fmaf(v.z, g_scale[cb + 2], g_shift[cb + 2]);
    v.w = fmaf(v.w, g_scale[cb + 3], g_shift[cb + 3]);
    y[t] = v;
}

// ---------------- launch ----------------
extern "C" void kernel_launch(void* const* d_in, const int* in_sizes, int n_in,
                              void* d_out, int out_size) {
    const float* x     = (const float*)d_in[0];
    const int*   src   = (const int*)d_in[1];
    const int*   dst   = (const int*)d_in[2];
    const float* W     = (const float*)d_in[3];
    const float* b     = (const float*)d_in[4];
    const float* Wr    = (const float*)d_in[5];
    const float* br    = (const float*)d_in[6];
    const float* gamma = (const float*)d_in[7];
    const float* beta  = (const float*)d_in[8];
    float* out = (float*)d_out;

    int N  = in_sizes[0] / D;
    int nE = in_sizes[1];
    int n4 = N * D4;

    const int SMEM = 196608;  // 48K floats
    cudaFuncSetAttribute(gemm_kernel, cudaFuncAttributeMaxDynamicSharedMemorySize, SMEM);

    zero_kernel<<<(N + 255) / 256, 256>>>(N);
    degree_kernel<<<(nE + 255) / 256, 256>>>(src, dst, nE);
    scan1_kernel<<<SCAN_NB, SCAN_BLK>>>(N);
    scan2_kernel<<<1, 32>>>();
    scan3_kernel<<<SCAN_NB, SCAN_BLK>>>(N);
    fill_kernel<<<(nE + 255) / 256, 256>>>(src, dst, nE);
    {
        long long threads = (long long)N * 32;
        int blocks = (int)((threads + 255) / 256);
        gather_kernel<<<blocks, 256>>>((const float4*)x, N);
    }
    int ntiles = (N + 63) / 64;
    gemm_kernel<<<ntiles, 256, SMEM>>>(x, W, b, Wr, br, out, N);
    bnstats_kernel<<<1, D>>>(gamma, beta, 1.0f / (float)N);
    normalize_kernel<<<(n4 + 255) / 256, 256>>>((float4*)out, n4);
}

// round 6
// speedup vs baseline: 2.1494x; 1.3736x over previous
#include <cuda_runtime.h>
#include <cuda_bf16.h>
#include <cstdint>

#define NMAX 50000
#define EMAX 800000
#define D 128
#define D4 32
#define BN_EPS 1e-5f
#define SCAN_BLK 1024
#define SCAN_NB  49
#define PITCH 272            // bytes per 128-bf16 row (256 + 16 pad): conflict-free frags

// ---------------- scratch ----------------
__device__ float4 g_agg[NMAX * D4];
__device__ int    g_deg_out[NMAX];
__device__ int    g_deg_in[NMAX];
__device__ int    g_incl[SCAN_NB * SCAN_BLK];
__device__ int    g_bsum[SCAN_NB];
__device__ int    g_boff[SCAN_NB];
__device__ int    g_rowstart[NMAX];
__device__ int    g_cursor[NMAX];
__device__ int    g_csrc[EMAX];
__device__ float  g_inv_in[NMAX];
__device__ float  g_inv_out[NMAX];
__device__ float  g_sum[D];
__device__ float  g_sq[D];
__device__ float  g_scale[D];
__device__ float  g_shift[D];
// pre-split weights, [n][k] layout (k contiguous) for mma row.col B operand
__device__ __nv_bfloat16 g_Whi[16384], g_Wlo[16384], g_Wrhi[16384], g_Wrlo[16384];

// ---------------- helpers ----------------
__device__ __forceinline__ uint32_t smem_u32(const void* p) {
    uint32_t a;
    asm("{ .reg .u64 t; cvta.to.shared.u64 t, %1; cvt.u32.u64 %0, t; }" : "=r"(a) : "l"(p));
    return a;
}
__device__ __forceinline__ uint32_t lds32(uint32_t a) {
    uint32_t v;
    asm volatile("ld.shared.b32 %0, [%1];" : "=r"(v) : "r"(a));
    return v;
}
__device__ __forceinline__ void sts128(uint32_t a, uint4 v) {
    asm volatile("st.shared.v4.b32 [%0], {%1,%2,%3,%4};"
                 :: "r"(a), "r"(v.x), "r"(v.y), "r"(v.z), "r"(v.w) : "memory");
}
__device__ __forceinline__ void mma_bf16(float* d, const uint32_t* a, uint32_t b0, uint32_t b1) {
    asm volatile(
        "mma.sync.aligned.m16n8k16.row.col.f32.bf16.bf16.f32 "
        "{%0,%1,%2,%3}, {%4,%5,%6,%7}, {%8,%9}, {%0,%1,%2,%3};"
        : "+f"(d[0]), "+f"(d[1]), "+f"(d[2]), "+f"(d[3])
        : "r"(a[0]), "r"(a[1]), "r"(a[2]), "r"(a[3]), "r"(b0), "r"(b1));
}
__device__ __forceinline__ void splitstore(float v, __nv_bfloat16* hi, __nv_bfloat16* lo) {
    __nv_bfloat16 h = __float2bfloat16_rn(v);
    *hi = h;
    *lo = __float2bfloat16_rn(v - __bfloat162float(h));
}

// ---------------- 1) zero ----------------
__global__ void zero_kernel(int N) {
    int i = blockIdx.x * blockDim.x + threadIdx.x;
    if (i < N) { g_deg_out[i] = 0; g_deg_in[i] = 0; }
    if (i < D) { g_sum[i] = 0.f; g_sq[i] = 0.f; }
}

// ---------------- 2) degrees ----------------
__global__ void degree_kernel(const int* __restrict__ src,
                              const int* __restrict__ dst, int nE) {
    int e = blockIdx.x * blockDim.x + threadIdx.x;
    if (e < nE) {
        atomicAdd(&g_deg_out[src[e]], 1);
        atomicAdd(&g_deg_in[dst[e]], 1);
    }
}

// ---------------- 3) scans ----------------
__global__ void scan1_kernel(int N) {
    __shared__ int sh[SCAN_BLK];
    int t = threadIdx.x;
    int i = blockIdx.x * SCAN_BLK + t;
    int v = (i < N) ? g_deg_in[i] : 0;
    sh[t] = v;
    __syncthreads();
    #pragma unroll
    for (int off = 1; off < SCAN_BLK; off <<= 1) {
        int tv = (t >= off) ? sh[t - off] : 0;
        __syncthreads();
        sh[t] += tv;
        __syncthreads();
    }
    g_incl[i] = sh[t];
    if (t == SCAN_BLK - 1) g_bsum[blockIdx.x] = sh[t];
}
__global__ void scan2_kernel() {
    __shared__ int sh[64];
    int t = threadIdx.x;
    int v = (t < SCAN_NB) ? g_bsum[t] : 0;
    sh[t] = v;
    __syncthreads();
    #pragma unroll
    for (int off = 1; off < 64; off <<= 1) {
        int tv = (t >= off) ? sh[t - off] : 0;
        __syncthreads();
        sh[t] += tv;
        __syncthreads();
    }
    if (t < SCAN_NB) g_boff[t] = sh[t] - v;
}
__global__ void scan3_kernel(int N) {
    int i = blockIdx.x * SCAN_BLK + threadIdx.x;
    if (i >= N) return;
    int din = g_deg_in[i];
    int rs = g_incl[i] - din + g_boff[blockIdx.x];
    g_rowstart[i] = rs;
    g_cursor[i]   = rs;
    g_inv_in[i]  = rsqrtf(fmaxf((float)din, 1.f));
    g_inv_out[i] = rsqrtf(fmaxf((float)g_deg_out[i], 1.f));
}

// ---------------- 4) CSR fill ----------------
__global__ void fill_kernel(const int* __restrict__ src,
                            const int* __restrict__ dst, int nE) {
    int e = blockIdx.x * blockDim.x + threadIdx.x;
    if (e < nE) {
        int pos = atomicAdd(&g_cursor[dst[e]], 1);
        g_csrc[pos] = src[e];
    }
}

// ---------------- 5) gather ----------------
__global__ void gather_kernel(const float4* __restrict__ x4, int N) {
    int w = (blockIdx.x * blockDim.x + threadIdx.x) >> 5;
    int lane = threadIdx.x & 31;
    if (w >= N) return;
    int start = g_rowstart[w];
    int deg   = g_deg_in[w];
    float4 acc = make_float4(0.f, 0.f, 0.f, 0.f);
    for (int base = 0; base < deg; base += 32) {
        int rem = deg - base;
        int cnt = rem < 32 ? rem : 32;
        int sIdx = 0;
        if (lane < cnt) sIdx = g_csrc[start + base + lane];
        #pragma unroll 4
        for (int j = 0; j < cnt; j++) {
            int s = __shfl_sync(0xffffffffu, sIdx, j);
            float sc = __ldg(&g_inv_out[s]);
            float4 v = x4[s * D4 + lane];
            acc.x = fmaf(v.x, sc, acc.x);
            acc.y = fmaf(v.y, sc, acc.y);
            acc.z = fmaf(v.z, sc, acc.z);
            acc.w = fmaf(v.w, sc, acc.w);
        }
    }
    float inv = g_inv_in[w];
    acc.x *= inv; acc.y *= inv; acc.z *= inv; acc.w *= inv;
    g_agg[w * D4 + lane] = acc;
}

// ---------------- 6) prep weights: split into bf16 hi/lo, [n][k] ----------------
__global__ void prepw_kernel(const float* __restrict__ W, const float* __restrict__ Wr) {
    int t = blockIdx.x * blockDim.x + threadIdx.x;
    if (t >= 16384) return;
    int k = t & 127;
    int n = t >> 7;
    int idx = n * 128 + k;
    splitstore(W[k * D + n],  &g_Whi[idx],  &g_Wlo[idx]);
    splitstore(Wr[k * D + n], &g_Wrhi[idx], &g_Wrlo[idx]);
}

// ---------------- 7) HMMA dual GEMM + relu + residual ----------------
// 256 threads = 8 warps in 4x2; warp tile 32 rows x 64 cols; bf16 hi/lo 3-term split.
__device__ __forceinline__ void compute_phase(
    uint32_t aHi, uint32_t aLo, uint32_t bHi, uint32_t bLo,
    float acc[2][8][4], int warpRow, int warpCol, int gID, int tig)
{
    for (int ks = 0; ks < 8; ks++) {
        uint32_t kb = (uint32_t)(ks * 32 + tig * 4);   // byte offset of k-pair
        uint32_t ahi[2][4], alo[2][4];
        #pragma unroll
        for (int rt = 0; rt < 2; rt++) {
            uint32_t r0 = (uint32_t)(warpRow + rt * 16 + gID);
            uint32_t b0 = r0 * PITCH + kb;
            ahi[rt][0] = lds32(aHi + b0);
            ahi[rt][1] = lds32(aHi + b0 + 8 * PITCH);
            ahi[rt][2] = lds32(aHi + b0 + 16);
            ahi[rt][3] = lds32(aHi + b0 + 8 * PITCH + 16);
            alo[rt][0] = lds32(aLo + b0);
            alo[rt][1] = lds32(aLo + b0 + 8 * PITCH);
            alo[rt][2] = lds32(aLo + b0 + 16);
            alo[rt][3] = lds32(aLo + b0 + 8 * PITCH + 16);
        }
        #pragma unroll
        for (int nt = 0; nt < 8; nt++) {
            uint32_t n0 = (uint32_t)(warpCol + nt * 8 + gID);
            uint32_t bb = n0 * PITCH + kb;
            uint32_t bh0 = lds32(bHi + bb), bh1 = lds32(bHi + bb + 16);
            uint32_t bl0 = lds32(bLo + bb), bl1 = lds32(bLo + bb + 16);
            #pragma unroll
            for (int rt = 0; rt < 2; rt++) {
                mma_bf16(acc[rt][nt], ahi[rt], bh0, bh1);
                mma_bf16(acc[rt][nt], ahi[rt], bl0, bl1);
                mma_bf16(acc[rt][nt], alo[rt], bh0, bh1);
            }
        }
    }
}

__global__ void __launch_bounds__(256, 1)
gemm_mma_kernel(const float4* __restrict__ x4,
                const float* __restrict__ b, const float* __restrict__ br,
                float* __restrict__ y, int N) {
    extern __shared__ char dsm[];
    uint32_t base = smem_u32(dsm);
    const uint32_t A_HI = base,            A_LO = base + 34816u;
    const uint32_t W_HI = base + 69632u,   W_LO = base + 104448u;
    const uint32_t WR_HI = base + 139264u, WR_LO = base + 174080u;

    __shared__ float sb[D], sbr[D];

    int tid = threadIdx.x;
    int lane = tid & 31, warp = tid >> 5;
    int gID = lane >> 2, tig = lane & 3;
    int warpRow = (warp >> 1) * 32;     // 0,32,64,96
    int warpCol = (warp & 1) * 64;      // 0,64
    int rowbase = blockIdx.x * 128;

    if (tid < D) { sb[tid] = b[tid]; sbr[tid] = br[tid]; }

    // copy pre-split weights into padded SMEM
    {
        const uint4* s0 = (const uint4*)g_Whi;  const uint4* s1 = (const uint4*)g_Wlo;
        const uint4* s2 = (const uint4*)g_Wrhi; const uint4* s3 = (const uint4*)g_Wrlo;
        #pragma unroll
        for (int i = tid; i < 2048; i += 256) {
            uint32_t n = (uint32_t)(i >> 4), ci = (uint32_t)(i & 15);
            uint32_t off = n * PITCH + ci * 16;
            sts128(W_HI + off, s0[i]);
            sts128(W_LO + off, s1[i]);
            sts128(WR_HI + off, s2[i]);
            sts128(WR_LO + off, s3[i]);
        }
    }

    // ---- phase 1: A = agg ----
    #pragma unroll
    for (int i = tid; i < 2048; i += 256) {
        int row = i >> 4, ch = i & 15;
        int gr = rowbase + row;
        float4 v0 = make_float4(0.f,0.f,0.f,0.f), v1 = v0;
        if (gr < N) { v0 = g_agg[gr * D4 + ch * 2]; v1 = g_agg[gr * D4 + ch * 2 + 1]; }
        __nv_bfloat16 hi[8], lo[8];
        splitstore(v0.x, hi+0, lo+0); splitstore(v0.y, hi+1, lo+1);
        splitstore(v0.z, hi+2, lo+2); splitstore(v0.w, hi+3, lo+3);
        splitstore(v1.x, hi+4, lo+4); splitstore(v1.y, hi+5, lo+5);
        splitstore(v1.z, hi+6, lo+6); splitstore(v1.w, hi+7, lo+7);
        uint32_t off = (uint32_t)row * PITCH + (uint32_t)ch * 16;
        sts128(A_HI + off, *(const uint4*)hi);
        sts128(A_LO + off, *(const uint4*)lo);
    }
    __syncthreads();

    float accG[2][8][4];
    #pragma unroll
    for (int rt = 0; rt < 2; rt++)
        #pragma unroll
        for (int nt = 0; nt < 8; nt++)
            #pragma unroll
            for (int j = 0; j < 4; j++) accG[rt][nt][j] = 0.f;

    compute_phase(A_HI, A_LO, W_HI, W_LO, accG, warpRow, warpCol, gID, tig);
    __syncthreads();

    // ---- phase 2: A = x ----
    #pragma unroll
    for (int i = tid; i < 2048; i += 256) {
        int row = i >> 4, ch = i & 15;
        int gr = rowbase + row;
        float4 v0 = make_float4(0.f,0.f,0.f,0.f), v1 = v0;
        if (gr < N) { v0 = x4[gr * D4 + ch * 2]; v1 = x4[gr * D4 + ch * 2 + 1]; }
        __nv_bfloat16 hi[8], lo[8];
        splitstore(v0.x, hi+0, lo+0); splitstore(v0.y, hi+1, lo+1);
        splitstore(v0.z, hi+2, lo+2); splitstore(v0.w, hi+3, lo+3);
        splitstore(v1.x, hi+4, lo+4); splitstore(v1.y, hi+5, lo+5);
        splitstore(v1.z, hi+6, lo+6); splitstore(v1.w, hi+7, lo+7);
        uint32_t off = (uint32_t)row * PITCH + (uint32_t)ch * 16;
        sts128(A_HI + off, *(const uint4*)hi);
        sts128(A_LO + off, *(const uint4*)lo);
    }
    __syncthreads();

    float accR[2][8][4];
    #pragma unroll
    for (int rt = 0; rt < 2; rt++)
        #pragma unroll
        for (int nt = 0; nt < 8; nt++)
            #pragma unroll
            for (int j = 0; j < 4; j++) accR[rt][nt][j] = 0.f;

    compute_phase(A_HI, A_LO, WR_HI, WR_LO, accR, warpRow, warpCol, gID, tig);

    // ---- epilogue: y = relu(G+b) + relu(R+br) ----
    #pragma unroll
    for (int rt = 0; rt < 2; rt++) {
        int gr0 = rowbase + warpRow + rt * 16 + gID;
        int gr1 = gr0 + 8;
        #pragma unroll
        for (int nt = 0; nt < 8; nt++) {
            int c0 = warpCol + nt * 8 + tig * 2;
            float bx = sb[c0], by = sb[c0 + 1];
            float brx = sbr[c0], bry = sbr[c0 + 1];
            if (gr0 < N) {
                float2 o;
                o.x = fmaxf(accG[rt][nt][0] + bx, 0.f) + fmaxf(accR[rt][nt][0] + brx, 0.f);
                o.y = fmaxf(accG[rt][nt][1] + by, 0.f) + fmaxf(accR[rt][nt][1] + bry, 0.f);
                *(float2*)(y + gr0 * D + c0) = o;
            }
            if (gr1 < N) {
                float2 o;
                o.x = fmaxf(accG[rt][nt][2] + bx, 0.f) + fmaxf(accR[rt][nt][2] + brx, 0.f);
                o.y = fmaxf(accG[rt][nt][3] + by, 0.f) + fmaxf(accR[rt][nt][3] + bry, 0.f);
                *(float2*)(y + gr1 * D + c0) = o;
            }
        }
    }
}

// ---------------- 8) BN column sums ----------------
__global__ void bnsum_kernel(const float4* __restrict__ y4, int N) {
    int q = threadIdx.x & 31, rg = threadIdx.x >> 5;
    float4 s  = make_float4(0.f,0.f,0.f,0.f);
    float4 ss = make_float4(0.f,0.f,0.f,0.f);
    for (int r = blockIdx.x * 8 + rg; r < N; r += gridDim.x * 8) {
        float4 v = y4[r * D4 + q];
        s.x += v.x; s.y += v.y; s.z += v.z; s.w += v.w;
        ss.x += v.x*v.x; ss.y += v.y*v.y; ss.z += v.z*v.z; ss.w += v.w*v.w;
    }
    __shared__ float shS[8][D], shQ[8][D];
    shS[rg][q*4+0] = s.x;  shS[rg][q*4+1] = s.y;  shS[rg][q*4+2] = s.z;  shS[rg][q*4+3] = s.w;
    shQ[rg][q*4+0] = ss.x; shQ[rg][q*4+1] = ss.y; shQ[rg][q*4+2] = ss.z; shQ[rg][q*4+3] = ss.w;
    __syncthreads();
    if (threadIdx.x < D) {
        float a = 0.f, c = 0.f;
        #pragma unroll
        for (int g = 0; g < 8; g++) { a += shS[g][threadIdx.x]; c += shQ[g][threadIdx.x]; }
        atomicAdd(&g_sum[threadIdx.x], a);
        atomicAdd(&g_sq[threadIdx.x],  c);
    }
}

// ---------------- 9) BN stats ----------------
__global__ void bnstats_kernel(const float* __restrict__ gamma,
                               const float* __restrict__ beta, float Ninv) {
    int i = threadIdx.x;
    float mean = g_sum[i] * Ninv;
    float var  = fmaxf(g_sq[i] * Ninv - mean * mean, 0.f);
    float istd = rsqrtf(var + BN_EPS);
    float sc = gamma[i] * istd;
    g_scale[i] = sc;
    g_shift[i] = beta[i] - mean * sc;
}

// ---------------- 10) normalize ----------------
__global__ void normalize_kernel(float4* __restrict__ y, int total4) {
    int t = blockIdx.x * blockDim.x + threadIdx.x;
    if (t >= total4) return;
    int cb = (t & 31) * 4;
    float4 v = y[t];
    v.x = fmaf(v.x, g_scale[cb + 0], g_shift[cb + 0]);
    v.y = fmaf(v.y, g_scale[cb + 1], g_shift[cb + 1]);
    v.z = fmaf(v.z, g_scale[cb + 2], g_shift[cb + 2]);
    v.w = fmaf(v.w, g_scale[cb + 3], g_shift[cb + 3]);
    y[t] = v;
}

// ---------------- launch ----------------
extern "C" void kernel_launch(void* const* d_in, const int* in_sizes, int n_in,
                              void* d_out, int out_size) {
    const float* x     = (const float*)d_in[0];
    const int*   src   = (const int*)d_in[1];
    const int*   dst   = (const int*)d_in[2];
    const float* W     = (const float*)d_in[3];
    const float* b     = (const float*)d_in[4];
    const float* Wr    = (const float*)d_in[5];
    const float* br    = (const float*)d_in[6];
    const float* gamma = (const float*)d_in[7];
    const float* beta  = (const float*)d_in[8];
    float* out = (float*)d_out;

    int N  = in_sizes[0] / D;
    int nE = in_sizes[1];
    int n4 = N * D4;

    const int DSMEM = 208896;   // 6 regions x 128 rows x 272B
    cudaFuncSetAttribute(gemm_mma_kernel, cudaFuncAttributeMaxDynamicSharedMemorySize, DSMEM);

    zero_kernel<<<(N + 255) / 256, 256>>>(N);
    degree_kernel<<<(nE + 255) / 256, 256>>>(src, dst, nE);
    scan1_kernel<<<SCAN_NB, SCAN_BLK>>>(N);
    scan2_kernel<<<1, 64>>>();
    scan3_kernel<<<SCAN_NB, SCAN_BLK>>>(N);
    fill_kernel<<<(nE + 255) / 256, 256>>>(src, dst, nE);
    prepw_kernel<<<64, 256>>>(W, Wr);
    {
        long long threads = (long long)N * 32;
        int blocks = (int)((threads + 255) / 256);
        gather_kernel<<<blocks, 256>>>((const float4*)x, N);
    }
    int ntiles = (N + 127) / 128;
    gemm_mma_kernel<<<ntiles, 256, DSMEM>>>((const float4*)x, b, br, out, N);
    bnsum_kernel<<<256, 256>>>((const float4*)out, N);
    bnstats_kernel<<<1, D>>>(gamma, beta, 1.0f / (float)N);
    normalize_kernel<<<(n4 + 255) / 256, 256>>>((float4*)out, n4);
}